// round 3
// baseline (speedup 1.0000x reference)
#include <cuda_runtime.h>

#define NB 4096
#define EPSV 1e-5f

// stage geometry
// conv1 out:  16 x 12 x 36  (6912)   pool1: 16 x 7 x 19 (2128)
// conv2 out:  32 x  7 x 19  (4256)   pool2: 32 x 4 x 10 (1280)
// conv3 out:  64 x  4 x 10  (2560)   pool3: 64 x 3 x  6 (1152)

__device__ float g_s1[NB * 6912];
__device__ float g_s2[NB * 4256];
__device__ float g_s3[NB * 2560];
__device__ float g_sum1[16], g_sq1[16], g_scale1[16], g_shift1[16];
__device__ float g_sum2[32], g_sq2[32], g_scale2[32], g_shift2[32];
__device__ float g_sum3[64], g_sq3[64], g_scale3[64], g_shift3[64];

__global__ void k_zero_stats() {
    int t = threadIdx.x;
    if (t < 16) { g_sum1[t] = 0.f; g_sq1[t] = 0.f; }
    if (t < 32) { g_sum2[t] = 0.f; g_sq2[t] = 0.f; }
    if (t < 64) { g_sum3[t] = 0.f; g_sq3[t] = 0.f; }
}

__global__ void k_finalize(const float* __restrict__ gamma,
                           const float* __restrict__ beta,
                           float invN, int stage) {
    int t = threadIdx.x;
    float *sum, *sq, *scale, *shift;
    int C;
    if (stage == 1)      { sum = g_sum1; sq = g_sq1; scale = g_scale1; shift = g_shift1; C = 16; }
    else if (stage == 2) { sum = g_sum2; sq = g_sq2; scale = g_scale2; shift = g_shift2; C = 32; }
    else                 { sum = g_sum3; sq = g_sq3; scale = g_scale3; shift = g_shift3; C = 64; }
    if (t < C) {
        float m = sum[t] * invN;
        float v = sq[t] * invN - m * m;
        float s = gamma[t] * rsqrtf(v + EPSV);
        scale[t] = s;
        shift[t] = beta[t] - m * s;
    }
}

// ---------------- stage 1: conv1 (2->16, 12x36) + stats ----------------
__global__ __launch_bounds__(256) void k_conv1(const float* __restrict__ x,
                                               const int* __restrict__ idx,
                                               const float* __restrict__ w1,
                                               const float* __restrict__ b1) {
    __shared__ float xs[864];    // 2 x 12 x 36
    __shared__ float ws[288];    // 16 x 2 x 9
    __shared__ float bs[16];
    __shared__ float outb[6912];
    __shared__ float ssum[16], ssq[16];
    int tid = threadIdx.x;
    int sample = blockIdx.x;
    int e = idx[sample];
    for (int j = tid; j < 864; j += 256) xs[j] = x[sample * 864 + j];
    for (int j = tid; j < 288; j += 256) ws[j] = w1[e * 288 + j];
    if (tid < 16) { bs[tid] = b1[e * 16 + tid]; ssum[tid] = 0.f; ssq[tid] = 0.f; }
    __syncthreads();

    if (tid < 192) {                      // 16 channels x 12 rows
        int c = tid / 12, h = tid % 12;
        float acc[36];
        float bias = bs[c];
        #pragma unroll
        for (int w = 0; w < 36; w++) acc[w] = bias;
        #pragma unroll
        for (int ci = 0; ci < 2; ci++) {
            #pragma unroll
            for (int kh = 0; kh < 3; kh++) {
                int ih = h + kh - 1;
                if (ih < 0 || ih >= 12) continue;
                const float* row = &xs[ci * 432 + ih * 36];
                const float* wk = &ws[(c * 2 + ci) * 9 + kh * 3];
                float w0 = wk[0], w1v = wk[1], w2v = wk[2];
                float r[38];
                r[0] = 0.f; r[37] = 0.f;
                #pragma unroll
                for (int k = 0; k < 36; k++) r[k + 1] = row[k];
                #pragma unroll
                for (int w = 0; w < 36; w++)
                    acc[w] += r[w] * w0 + r[w + 1] * w1v + r[w + 2] * w2v;
            }
        }
        float ls = 0.f, lq = 0.f;
        #pragma unroll
        for (int w = 0; w < 36; w++) {
            float v = acc[w];
            outb[c * 432 + h * 36 + w] = v;
            ls += v; lq += v * v;
        }
        atomicAdd(&ssum[c], ls);
        atomicAdd(&ssq[c], lq);
    }
    __syncthreads();
    for (int j = tid; j < 6912; j += 256) g_s1[sample * 6912 + j] = outb[j];
    if (tid < 16) { atomicAdd(&g_sum1[tid], ssum[tid]); atomicAdd(&g_sq1[tid], ssq[tid]); }
}

// -------- stage 2: bn1+relu+pool1 -> conv2 (16->32, 7x19) + stats --------
__global__ __launch_bounds__(256) void k_stage2(const int* __restrict__ idx,
                                                const float* __restrict__ w2,
                                                const float* __restrict__ b2) {
    extern __shared__ float sm[];
    float* p1   = sm;              // 16*7*19 = 2128
    float* wsh  = p1 + 2128;       // 32*16*9 = 4608
    float* bsh  = wsh + 4608;      // 32
    float* outb = bsh + 32;        // 32*7*19 = 4256
    float* ssum = outb + 4256;     // 32
    float* ssq  = ssum + 32;       // 32
    int tid = threadIdx.x;
    int sample = blockIdx.x;
    int e = idx[sample];
    for (int j = tid; j < 4608; j += 256) wsh[j] = w2[e * 4608 + j];
    if (tid < 32) { bsh[tid] = b2[e * 32 + tid]; ssum[tid] = 0.f; ssq[tid] = 0.f; }
    const float* s1p = &g_s1[sample * 6912];
    for (int j = tid; j < 2128; j += 256) {
        int c = j / 133, r = j % 133, oh = r / 19, ow = r % 19;
        float sc = g_scale1[c], sh = g_shift1[c];
        float m = -1e30f;
        #pragma unroll
        for (int dh = 0; dh < 2; dh++) {
            int ih = 2 * oh - 1 + dh;
            if (ih < 0 || ih >= 12) continue;
            #pragma unroll
            for (int dw = 0; dw < 2; dw++) {
                int iw = 2 * ow - 1 + dw;
                if (iw < 0 || iw >= 36) continue;
                float v = fmaxf(s1p[c * 432 + ih * 36 + iw] * sc + sh, 0.f);
                m = fmaxf(m, v);
            }
        }
        p1[j] = m;
    }
    __syncthreads();

    if (tid < 224) {                       // 32 channels x 7 rows
        int c = tid / 7, h = tid % 7;
        float acc[19];
        float bias = bsh[c];
        #pragma unroll
        for (int w = 0; w < 19; w++) acc[w] = bias;
        for (int ci = 0; ci < 16; ci++) {
            #pragma unroll
            for (int kh = 0; kh < 3; kh++) {
                int ih = h + kh - 1;
                if (ih < 0 || ih >= 7) continue;
                const float* row = &p1[ci * 133 + ih * 19];
                const float* wk = &wsh[(c * 16 + ci) * 9 + kh * 3];
                float w0 = wk[0], w1v = wk[1], w2v = wk[2];
                float r[21];
                r[0] = 0.f; r[20] = 0.f;
                #pragma unroll
                for (int k = 0; k < 19; k++) r[k + 1] = row[k];
                #pragma unroll
                for (int w = 0; w < 19; w++)
                    acc[w] += r[w] * w0 + r[w + 1] * w1v + r[w + 2] * w2v;
            }
        }
        float ls = 0.f, lq = 0.f;
        #pragma unroll
        for (int w = 0; w < 19; w++) {
            float v = acc[w];
            outb[c * 133 + h * 19 + w] = v;
            ls += v; lq += v * v;
        }
        atomicAdd(&ssum[c], ls);
        atomicAdd(&ssq[c], lq);
    }
    __syncthreads();
    float* s2p = &g_s2[sample * 4256];
    for (int j = tid; j < 4256; j += 256) s2p[j] = outb[j];
    if (tid < 32) { atomicAdd(&g_sum2[tid], ssum[tid]); atomicAdd(&g_sq2[tid], ssq[tid]); }
}

// -------- stage 3: bn2+relu+pool2 -> conv3 (32->64, 4x10) + stats --------
__global__ __launch_bounds__(256) void k_stage3(const int* __restrict__ idx,
                                                const float* __restrict__ w3,
                                                const float* __restrict__ b3) {
    extern __shared__ float sm[];
    float* p2   = sm;               // 32*4*10 = 1280
    float* wsh  = p2 + 1280;        // 64*32*9 = 18432
    float* bsh  = wsh + 18432;      // 64
    float* outb = bsh + 64;         // 64*4*10 = 2560
    float* ssum = outb + 2560;      // 64
    float* ssq  = ssum + 64;        // 64
    int tid = threadIdx.x;
    int sample = blockIdx.x;
    int e = idx[sample];
    for (int j = tid; j < 18432; j += 256) wsh[j] = w3[e * 18432 + j];
    if (tid < 64) { bsh[tid] = b3[e * 64 + tid]; ssum[tid] = 0.f; ssq[tid] = 0.f; }
    const float* s2p = &g_s2[sample * 4256];
    for (int j = tid; j < 1280; j += 256) {
        int c = j / 40, r = j % 40, oh = r / 10, ow = r % 10;
        float sc = g_scale2[c], sh = g_shift2[c];
        float m = -1e30f;
        #pragma unroll
        for (int dh = 0; dh < 2; dh++) {
            int ih = 2 * oh - 1 + dh;
            if (ih < 0 || ih >= 7) continue;
            #pragma unroll
            for (int dw = 0; dw < 2; dw++) {
                int iw = 2 * ow - 1 + dw;
                if (iw < 0 || iw >= 19) continue;
                float v = fmaxf(s2p[c * 133 + ih * 19 + iw] * sc + sh, 0.f);
                m = fmaxf(m, v);
            }
        }
        p2[j] = m;
    }
    __syncthreads();

    {                                        // 64 channels x 4 rows = 256 tasks
        int c = tid >> 2, h = tid & 3;
        float acc[10];
        float bias = bsh[c];
        #pragma unroll
        for (int w = 0; w < 10; w++) acc[w] = bias;
        for (int ci = 0; ci < 32; ci++) {
            #pragma unroll
            for (int kh = 0; kh < 3; kh++) {
                int ih = h + kh - 1;
                if (ih < 0 || ih >= 4) continue;
                const float* row = &p2[ci * 40 + ih * 10];
                const float* wk = &wsh[(c * 32 + ci) * 9 + kh * 3];
                float w0 = wk[0], w1v = wk[1], w2v = wk[2];
                float r[12];
                r[0] = 0.f; r[11] = 0.f;
                #pragma unroll
                for (int k = 0; k < 10; k++) r[k + 1] = row[k];
                #pragma unroll
                for (int w = 0; w < 10; w++)
                    acc[w] += r[w] * w0 + r[w + 1] * w1v + r[w + 2] * w2v;
            }
        }
        float ls = 0.f, lq = 0.f;
        #pragma unroll
        for (int w = 0; w < 10; w++) {
            float v = acc[w];
            outb[c * 40 + h * 10 + w] = v;
            ls += v; lq += v * v;
        }
        atomicAdd(&ssum[c], ls);
        atomicAdd(&ssq[c], lq);
    }
    __syncthreads();
    float* s3p = &g_s3[sample * 2560];
    for (int j = tid; j < 2560; j += 256) s3p[j] = outb[j];
    if (tid < 64) { atomicAdd(&g_sum3[tid], ssum[tid]); atomicAdd(&g_sq3[tid], ssq[tid]); }
}

// -------- stage 4: bn3+relu+pool3 -> fc1+relu -> fc2, 16 samples/block --------
// dynamic smem: X 16 x 578 + WS 64 x 66 + H 16 x 64 = 14496 floats = 57984 B
#define XHS 578   // 576 + 2 pad
#define WTS 66    // 64 + 2 pad
__global__ __launch_bounds__(256) void k_stage4(const float* __restrict__ fw1,
                                                const float* __restrict__ fb1,
                                                const float* __restrict__ fw2,
                                                float* __restrict__ out) {
    extern __shared__ float sm4[];
    float* X  = sm4;                  // 16 * 578
    float* WS = X + 16 * XHS;         // 64 * 66
    float* H  = WS + 64 * WTS;        // 16 * 64
    int tid = threadIdx.x;
    int s0 = blockIdx.x * 16;

    int o = tid >> 2, sg = tid & 3;
    float bias = fb1[o];
    float acc0 = bias, acc1 = bias, acc2 = bias, acc3 = bias;

    for (int half = 0; half < 2; half++) {
        int f0 = half * 576;
        __syncthreads();   // protect X reuse across halves
        // build pooled features f0..f0+575 for 16 samples
        for (int j = tid; j < 16 * 576; j += 256) {
            int sl = j / 576, f = f0 + (j % 576);
            int c = f / 18, r = f % 18, oh = r / 6, ow = r % 6;
            const float* s3p = &g_s3[(s0 + sl) * 2560 + c * 40];
            float sc = g_scale3[c], sh = g_shift3[c];
            float m = -1e30f;
            #pragma unroll
            for (int dh = 0; dh < 2; dh++) {
                int ih = 2 * oh - 1 + dh;
                if (ih < 0 || ih >= 4) continue;
                #pragma unroll
                for (int dw = 0; dw < 2; dw++) {
                    int iw = 2 * ow - 1 + dw;
                    if (iw < 0 || iw >= 10) continue;
                    float v = fmaxf(s3p[ih * 10 + iw] * sc + sh, 0.f);
                    m = fmaxf(m, v);
                }
            }
            X[sl * XHS + (j % 576)] = m;
        }
        for (int k0 = 0; k0 < 576; k0 += 64) {
            // load W tile 64 x 64
            for (int j = tid; j < 64 * 64; j += 256) {
                int rr = j >> 6, cc = j & 63;
                WS[rr * WTS + cc] = fw1[rr * 1152 + f0 + k0 + cc];
            }
            __syncthreads();
            const float* x0 = &X[(sg * 4 + 0) * XHS + k0];
            const float* x1 = &X[(sg * 4 + 1) * XHS + k0];
            const float* x2 = &X[(sg * 4 + 2) * XHS + k0];
            const float* x3 = &X[(sg * 4 + 3) * XHS + k0];
            const float* wrow = &WS[o * WTS];
            #pragma unroll 16
            for (int kk = 0; kk < 64; kk++) {
                float wv = wrow[kk];
                acc0 += wv * x0[kk];
                acc1 += wv * x1[kk];
                acc2 += wv * x2[kk];
                acc3 += wv * x3[kk];
            }
            __syncthreads();   // compute done before next W tile overwrite
        }
    }
    H[(sg * 4 + 0) * 64 + o] = fmaxf(acc0, 0.f);
    H[(sg * 4 + 1) * 64 + o] = fmaxf(acc1, 0.f);
    H[(sg * 4 + 2) * 64 + o] = fmaxf(acc2, 0.f);
    H[(sg * 4 + 3) * 64 + o] = fmaxf(acc3, 0.f);
    __syncthreads();

    int w = tid >> 5, lane = tid & 31;
    #pragma unroll
    for (int rep = 0; rep < 2; rep++) {
        int s = w + rep * 8;
        float v = H[s * 64 + lane] * fw2[lane] + H[s * 64 + lane + 32] * fw2[lane + 32];
        #pragma unroll
        for (int off = 16; off > 0; off >>= 1) v += __shfl_down_sync(0xffffffffu, v, off);
        if (lane == 0) out[s0 + s] = v;
    }
}

extern "C" void kernel_launch(void* const* d_in, const int* in_sizes, int n_in,
                              void* d_out, int out_size) {
    const float* x   = (const float*)d_in[0];
    const int*   idx = (const int*)d_in[1];
    const float* w1  = (const float*)d_in[2];
    const float* b1  = (const float*)d_in[3];
    const float* w2  = (const float*)d_in[4];
    const float* b2  = (const float*)d_in[5];
    const float* w3  = (const float*)d_in[6];
    const float* b3  = (const float*)d_in[7];
    const float* g1  = (const float*)d_in[8];
    const float* be1 = (const float*)d_in[9];
    const float* g2  = (const float*)d_in[10];
    const float* be2 = (const float*)d_in[11];
    const float* g3  = (const float*)d_in[12];
    const float* be3 = (const float*)d_in[13];
    const float* fw1 = (const float*)d_in[14];
    const float* fb1 = (const float*)d_in[15];
    const float* fw2 = (const float*)d_in[16];
    float* out = (float*)d_out;

    const int SM2 = (2128 + 4608 + 32 + 4256 + 64) * 4;            // 44352
    const int SM3 = (1280 + 18432 + 64 + 2560 + 128) * 4;          // 89856
    const int SM4 = (16 * XHS + 64 * WTS + 16 * 64) * 4;           // 57984
    cudaFuncSetAttribute(k_stage3, cudaFuncAttributeMaxDynamicSharedMemorySize, SM3);
    cudaFuncSetAttribute(k_stage4, cudaFuncAttributeMaxDynamicSharedMemorySize, SM4);

    k_zero_stats<<<1, 64>>>();
    k_conv1<<<NB, 256>>>(x, idx, w1, b1);
    k_finalize<<<1, 64>>>(g1, be1, 1.f / (4096.f * 432.f), 1);
    k_stage2<<<NB, 256, SM2>>>(idx, w2, b2);
    k_finalize<<<1, 64>>>(g2, be2, 1.f / (4096.f * 133.f), 2);
    k_stage3<<<NB, 256, SM3>>>(idx, w3, b3);
    k_finalize<<<1, 64>>>(g3, be3, 1.f / (4096.f * 40.f), 3);
    k_stage4<<<256, 256, SM4>>>(fw1, fb1, fw2, out);
}